// round 2
// baseline (speedup 1.0000x reference)
#include <cuda_runtime.h>
#include <cuda_bf16.h>
#include <cstdint>

// CartesianToDihedral: (1024, 2048, 3, 3) f32 -> (angles (1024,12282), first_three (1024,9))
//
// x = in.reshape(1024, 6144, 3). For window i in [0, 6141):
//   a=x[i], b=x[i+1], c=x[i+2], d=x[i+3]
//   bc = normalize(b - c + 1e-8)          (norm clipped at 1e-12)
//   n1 = cross(a-b, bc); n2 = cross(bc, c-d)
//   xc = dot(n1,n2); yc = dot(cross(n1,bc), n2)
//   dih = atan2(yc, xc + 1e-8)
//   out: sin(dih) at [b,i], cos(dih) at [b,6141+i]
// first_three: x[b,0:3,:] -> 9 floats per batch, appended after angles.

namespace {
constexpr int B_SZ        = 1024;
constexpr int PTS_PER_ROW = 6144;                 // 2048*3
constexpr int FLT_PER_ROW = PTS_PER_ROW * 3;      // 18432
constexpr int NWIN        = PTS_PER_ROW - 3;      // 6141
constexpr int OUT_STRIDE  = 2 * NWIN;             // 12282
constexpr int WPB         = 256;                  // windows per block
constexpr int CHUNKS      = (NWIN + WPB - 1) / WPB;   // 24
constexpr int TILE_FLTS   = (WPB + 3) * 3;        // 777
constexpr int TILE_PAD    = 780;                  // pad to float4 multiple
constexpr int TILE_V4     = TILE_PAD / 4;         // 195
constexpr long long TOTAL_IN = (long long)B_SZ * FLT_PER_ROW;  // 18,874,368
}

__global__ __launch_bounds__(WPB)
void dihedral_kernel(const float* __restrict__ in, float* __restrict__ out) {
    __shared__ float s[TILE_PAD];

    const int bid   = blockIdx.x;
    const int batch = bid / CHUNKS;
    const int chunk = bid - batch * CHUNKS;
    const int w0    = chunk * WPB;

    const long long rowBase  = (long long)batch * FLT_PER_ROW;
    const long long tileBase = rowBase + (long long)w0 * 3;   // multiple of 4 floats

    // Cooperative aligned float4 tile load (overlap 3 points with next chunk).
    const float4* in4 = reinterpret_cast<const float4*>(in + tileBase);
    #pragma unroll
    for (int t = threadIdx.x; t < TILE_V4; t += WPB) {
        long long gf = tileBase + (long long)t * 4;
        float4 v;
        if (gf + 4 <= TOTAL_IN) {
            v = in4[t];
        } else {  // only the final block's tail (3 float4s) can trip this
            v = make_float4(0.f, 0.f, 0.f, 0.f);
            const float* p = in + gf;
            if (gf + 0 < TOTAL_IN) v.x = p[0];
            if (gf + 1 < TOTAL_IN) v.y = p[1];
            if (gf + 2 < TOTAL_IN) v.z = p[2];
        }
        reinterpret_cast<float4*>(s)[t] = v;
    }
    __syncthreads();

    const int i = w0 + threadIdx.x;
    if (i < NWIN) {
        const float* p = s + threadIdx.x * 3;   // stride-3 -> conflict-free
        const float ax = p[0],  ay = p[1],  az = p[2];
        const float bx = p[3],  by = p[4],  bz = p[5];
        const float cx = p[6],  cy = p[7],  cz = p[8];
        const float dx = p[9],  dy = p[10], dz = p[11];

        // bc = normalize(b - c + 1e-8)
        float ux = bx - cx + 1e-8f;
        float uy = by - cy + 1e-8f;
        float uz = bz - cz + 1e-8f;
        float un = sqrtf(fmaf(ux, ux, fmaf(uy, uy, uz * uz)));
        float inv = 1.0f / fmaxf(un, 1e-12f);
        ux *= inv; uy *= inv; uz *= inv;

        // ab = a - b ; cd = c - d
        const float abx = ax - bx, aby = ay - by, abz = az - bz;
        const float cdx = cx - dx, cdy = cy - dy, cdz = cz - dz;

        // n1 = cross(ab, bc)
        const float n1x = aby * uz - abz * uy;
        const float n1y = abz * ux - abx * uz;
        const float n1z = abx * uy - aby * ux;
        // n2 = cross(bc, cd)
        const float n2x = uy * cdz - uz * cdy;
        const float n2y = uz * cdx - ux * cdz;
        const float n2z = ux * cdy - uy * cdx;
        // m = cross(n1, bc)
        const float mx = n1y * uz - n1z * uy;
        const float my = n1z * ux - n1x * uz;
        const float mz = n1x * uy - n1y * ux;

        const float xc = fmaf(n1x, n2x, fmaf(n1y, n2y, n1z * n2z)) + 1e-8f;
        const float yc = fmaf(mx,  n2x, fmaf(my,  n2y, mz  * n2z));

        // sin(atan2(yc,xc)) = yc * rsqrt(xc^2+yc^2); cos = xc * rsqrt(...)
        const float r2 = fmaf(xc, xc, yc * yc);
        float sv, cv;
        if (r2 > 0.0f) {
            const float rinv = rsqrtf(r2);
            sv = yc * rinv;
            cv = xc * rinv;
        } else {               // atan2(0,0) = 0
            sv = 0.0f;
            cv = 1.0f;
        }

        const long long ob = (long long)batch * OUT_STRIDE;
        out[ob + i]        = sv;
        out[ob + NWIN + i] = cv;
    }

    // first_three: x[b, 0:3, :] = first 9 floats of the row, appended after angles.
    if (chunk == 0 && threadIdx.x < 9) {
        out[(long long)B_SZ * OUT_STRIDE + (long long)batch * 9 + threadIdx.x] =
            in[rowBase + threadIdx.x];
    }
}

extern "C" void kernel_launch(void* const* d_in, const int* in_sizes, int n_in,
                              void* d_out, int out_size) {
    const float* in = (const float*)d_in[0];
    float* out = (float*)d_out;
    dihedral_kernel<<<B_SZ * CHUNKS, WPB>>>(in, out);
}

// round 3
// speedup vs baseline: 1.6365x; 1.6365x over previous
#include <cuda_runtime.h>
#include <cuda_bf16.h>
#include <cstdint>

// CartesianToDihedral: (1024, 2048, 3, 3) f32 -> (angles (1024,12282), first_three (1024,9))
// Register-only version: 4 windows per thread, aligned float4 global loads,
// shared edge vectors, no shared memory, no syncthreads.

namespace {
constexpr int B_SZ        = 1024;
constexpr int PTS_PER_ROW = 6144;                 // 2048*3
constexpr int FLT_PER_ROW = PTS_PER_ROW * 3;      // 18432
constexpr int NWIN        = PTS_PER_ROW - 3;      // 6141
constexpr int OUT_STRIDE  = 2 * NWIN;             // 12282
constexpr int W           = 4;                    // windows per thread
constexpr int TPB         = 256;
constexpr int WIN_PER_BLK = W * TPB;              // 1024
constexpr int CHUNKS      = 6;                    // 6*1024 = 6144 >= 6141
constexpr long long TOTAL_IN = (long long)B_SZ * FLT_PER_ROW;  // 18,874,368
}

__device__ __forceinline__ void dihedral_core(
    const float* e0, const float* e1, const float* e2,  // edges: ab, bc_raw(-eps), cd
    float& sv, float& cv)
{
    // bc = normalize(e1 + 1e-8)
    const float ux0 = e1[0] + 1e-8f;
    const float uy0 = e1[1] + 1e-8f;
    const float uz0 = e1[2] + 1e-8f;
    const float rinv = rsqrtf(fmaf(ux0, ux0, fmaf(uy0, uy0, uz0 * uz0)));
    const float ux = ux0 * rinv, uy = uy0 * rinv, uz = uz0 * rinv;

    // n1 = cross(e0, u)
    const float n1x = fmaf(e0[1], uz, -e0[2] * uy);
    const float n1y = fmaf(e0[2], ux, -e0[0] * uz);
    const float n1z = fmaf(e0[0], uy, -e0[1] * ux);
    // n2 = cross(u, e2)
    const float n2x = fmaf(uy, e2[2], -uz * e2[1]);
    const float n2y = fmaf(uz, e2[0], -ux * e2[2]);
    const float n2z = fmaf(ux, e2[1], -uy * e2[0]);
    // m = cross(n1, u)
    const float mx = fmaf(n1y, uz, -n1z * uy);
    const float my = fmaf(n1z, ux, -n1x * uz);
    const float mz = fmaf(n1x, uy, -n1y * ux);

    const float xc = fmaf(n1x, n2x, fmaf(n1y, n2y, fmaf(n1z, n2z, 1e-8f)));
    const float yc = fmaf(mx,  n2x, fmaf(my,  n2y,  mz * n2z));

    const float r2 = fmaf(xc, xc, yc * yc);
    if (r2 > 0.0f) {
        const float ri = rsqrtf(r2);
        sv = yc * ri;
        cv = xc * ri;
    } else {
        sv = 0.0f;  // atan2(0,0) = 0
        cv = 1.0f;
    }
}

__global__ __launch_bounds__(TPB)
void dihedral_kernel(const float* __restrict__ in, float* __restrict__ out) {
    const int bid   = blockIdx.x;
    const int batch = bid / CHUNKS;
    const int chunk = bid - batch * CHUNKS;
    const int gw0   = chunk * WIN_PER_BLK + threadIdx.x * W;  // first window

    const long long rowBase = (long long)batch * FLT_PER_ROW;
    const long long fbase   = rowBase + (long long)gw0 * 3;   // multiple of 4

    // Load 7 points = 21 floats (24 with pad) as 6 aligned float4s.
    float f[24];
    if (fbase + 24 <= TOTAL_IN) {                 // all but one thread in the grid
        const float4* p4 = reinterpret_cast<const float4*>(in + fbase);
        #pragma unroll
        for (int t = 0; t < 6; t++) {
            const float4 v = p4[t];
            f[4*t+0] = v.x; f[4*t+1] = v.y; f[4*t+2] = v.z; f[4*t+3] = v.w;
        }
    } else {                                      // tail thread of the very last block
        #pragma unroll
        for (int t = 0; t < 24; t++)
            f[t] = (fbase + t < TOTAL_IN) ? in[fbase + t] : 0.0f;
    }

    // Edges e_j = p_j - p_{j+1}, j = 0..5
    float e[6][3];
    #pragma unroll
    for (int j = 0; j < 6; j++) {
        e[j][0] = f[3*j+0] - f[3*j+3];
        e[j][1] = f[3*j+1] - f[3*j+4];
        e[j][2] = f[3*j+2] - f[3*j+5];
    }

    float sv[W], cv[W];
    #pragma unroll
    for (int w = 0; w < W; w++)
        dihedral_core(e[w], e[w+1], e[w+2], sv[w], cv[w]);

    const long long ob = (long long)batch * OUT_STRIDE;

    if (gw0 + W <= NWIN) {
        // sin: base ob+gw0 is even & 8B-aligned -> two float2 stores
        float2* s2 = reinterpret_cast<float2*>(out + ob + gw0);
        s2[0] = make_float2(sv[0], sv[1]);
        s2[1] = make_float2(sv[2], sv[3]);
        // cos: offset NWIN (odd) -> scalar stores (warp-contiguous, coalesces in L2)
        float* cp = out + ob + NWIN + gw0;
        cp[0] = cv[0]; cp[1] = cv[1]; cp[2] = cv[2]; cp[3] = cv[3];
    } else {
        #pragma unroll
        for (int w = 0; w < W; w++) {
            if (gw0 + w < NWIN) {
                out[ob + gw0 + w]        = sv[w];
                out[ob + NWIN + gw0 + w] = cv[w];
            }
        }
    }

    // first_three: 9 floats per batch appended after all angle rows.
    if (chunk == 0 && threadIdx.x < 9) {
        out[(long long)B_SZ * OUT_STRIDE + (long long)batch * 9 + threadIdx.x] =
            in[rowBase + threadIdx.x];
    }
}

extern "C" void kernel_launch(void* const* d_in, const int* in_sizes, int n_in,
                              void* d_out, int out_size) {
    const float* in = (const float*)d_in[0];
    float* out = (float*)d_out;
    dihedral_kernel<<<B_SZ * CHUNKS, TPB>>>(in, out);
}